// round 2
// baseline (speedup 1.0000x reference)
#include <cuda_runtime.h>

// Problem constants (shapes fixed by the dataset instance)
#define BN      16
#define BATCH   4
#define HW      65536            // 256*256
#define PS4     (HW / 4)         // plane stride in float4
#define CO      134              // output channels: 3 nocs + 1 mask + 48 loc + 48 rot + 18 skin + 16 js
#define CT      101              // tar channels:    3 nocs + 1 mask + 48 loc + 48 rot + 1 seg
#define THRESH  0.7f

// Accumulator layout (doubles):
//  [0]                  mask-loss sum
//  [1]                  skin-loss sum
//  [2 + b*9 + 0..2]     nocs:    masked-sum, count, total-sum
//  [2 + b*9 + 3..5]     loc_map: masked-sum, count, total-sum
//  [2 + b*9 + 6..8]     rot_map: masked-sum, count, total-sum
//  [38 + (b*16+j)*7]    pose: denom, loc_num[3], rot_num[3]
#define NACC 486

__device__ double g_acc[NACC];

__global__ void zero_acc_kernel() {
    int i = blockIdx.x * blockDim.x + threadIdx.x;
    if (i < NACC) g_acc[i] = 0.0;
}

__device__ __forceinline__ float sigm(float x) {
    return __fdividef(1.0f, 1.0f + __expf(-x));
}

__device__ __forceinline__ void ld4(const float4* __restrict__ p, float* r) {
    float4 t = *p;
    r[0] = t.x; r[1] = t.y; r[2] = t.z; r[3] = t.w;
}

// warp-reduce then one shared atomic from lane 0
__device__ __forceinline__ void redAdd(float* s, int idx, float v) {
#pragma unroll
    for (int o = 16; o; o >>= 1) v += __shfl_xor_sync(0xffffffffu, v, o);
    if ((threadIdx.x & 31) == 0) atomicAdd(&s[idx], v);
}

__global__ __launch_bounds__(256)
void main_kernel(const float* __restrict__ outp, const float* __restrict__ tarp) {
    __shared__ float s[NACC];
    for (int i = threadIdx.x; i < NACC; i += 256) s[i] = 0.0f;
    __syncthreads();

    const int b  = blockIdx.x >> 6;                       // 64 blocks per image
    const int q4 = ((blockIdx.x & 63) << 8) + threadIdx.x; // float4 index within plane

    const float4* O = (const float4*)outp + (size_t)b * CO * PS4 + q4;
    const float4* T = (const float4*)tarp + (size_t)b * CT * PS4 + q4;

    const int NB = 2 + b * 9;
    const int PB = 38 + b * 112;

    // ---- masks ----
    float tm[4]; ld4(T + 3 * PS4, tm);
    float ml[4]; ld4(O + 3 * PS4, ml);

    // ---- mask BCE:  sum of  log_sigmoid(x) - (1-tm)*x  (negated in finalize) ----
    {
        float msum = 0.0f;
#pragma unroll
        for (int i = 0; i < 4; i++) {
            float x  = ml[i];
            float ls = fminf(x, 0.0f) - __logf(1.0f + __expf(-fabsf(x)));
            msum += ls - (1.0f - tm[i]) * x;
        }
        redAdd(s, 0, msum);
    }

    // ---- nocs masked L2 (norm over 3 raw channels) ----
    {
        float acc[4] = {0.f, 0.f, 0.f, 0.f};
#pragma unroll
        for (int c = 0; c < 3; c++) {
            float a[4], t[4];
            ld4(O + c * PS4, a);
            ld4(T + c * PS4, t);
#pragma unroll
            for (int i = 0; i < 4; i++) { float d = a[i] - t[i]; acc[i] += d * d; }
        }
        float ms = 0.f, cnt = 0.f, ts = 0.f;
#pragma unroll
        for (int i = 0; i < 4; i++) {
            float dn = sqrtf(acc[i]);
            ts += dn;
            if (tm[i] > THRESH && dn != 0.0f) { ms += dn; cnt += 1.0f; }
        }
        redAdd(s, NB + 0, ms);
        redAdd(s, NB + 1, cnt);
        redAdd(s, NB + 2, ts);
    }

    // ---- joint loop: loc/rot map norms (48-dim) + pose numerators/denominators ----
    {
        float locn[4] = {0.f, 0.f, 0.f, 0.f};
        float rotn[4] = {0.f, 0.f, 0.f, 0.f};

#pragma unroll 1
        for (int j = 0; j < BN; j++) {
            float jsr[4]; ld4(O + (118 + j) * PS4, jsr);
            float sj[4];     // sigma(js) * mask
            float sjm[4];    // sigma(js) * mask^2   (numerator weight)
            float dsum = 0.0f;
#pragma unroll
            for (int i = 0; i < 4; i++) {
                sj[i]  = sigm(jsr[i]) * tm[i];
                sjm[i] = sj[i] * tm[i];
                dsum  += sj[i];
            }
            redAdd(s, PB + j * 7, dsum);

#pragma unroll
            for (int c = 0; c < 3; c++) {
                // loc
                {
                    float pl[4], tl[4];
                    ld4(O + (4 + j * 3 + c) * PS4, pl);
                    ld4(T + (4 + j * 3 + c) * PS4, tl);
                    float num = 0.0f;
#pragma unroll
                    for (int i = 0; i < 4; i++) {
                        float p_ = sigm(pl[i]);
                        float d  = p_ - sigm(tl[i]);
                        locn[i] += d * d;
                        num += p_ * sjm[i];
                    }
                    redAdd(s, PB + j * 7 + 1 + c, num);
                }
                // rot
                {
                    float pr[4], tr[4];
                    ld4(O + (52 + j * 3 + c) * PS4, pr);
                    ld4(T + (52 + j * 3 + c) * PS4, tr);
                    float num = 0.0f;
#pragma unroll
                    for (int i = 0; i < 4; i++) {
                        float p_ = sigm(pr[i]);
                        float d  = p_ - sigm(tr[i]);
                        rotn[i] += d * d;
                        num += p_ * sjm[i];
                    }
                    redAdd(s, PB + j * 7 + 4 + c, num);
                }
            }
        }

        float lms = 0.f, lcnt = 0.f, lts = 0.f;
        float rms = 0.f, rcnt = 0.f, rts = 0.f;
#pragma unroll
        for (int i = 0; i < 4; i++) {
            float dl = sqrtf(locn[i]);
            lts += dl;
            if (tm[i] > THRESH && dl != 0.0f) { lms += dl; lcnt += 1.0f; }
            float dr = sqrtf(rotn[i]);
            rts += dr;
            if (tm[i] > THRESH && dr != 0.0f) { rms += dr; rcnt += 1.0f; }
        }
        redAdd(s, NB + 3, lms);
        redAdd(s, NB + 4, lcnt);
        redAdd(s, NB + 5, lts);
        redAdd(s, NB + 6, rms);
        redAdd(s, NB + 7, rcnt);
        redAdd(s, NB + 8, rts);
    }

    // ---- skin cross-entropy over 18 classes ----
    {
        float tl0[4]; ld4(T + 100 * PS4, tl0);
        int lab[4];
#pragma unroll
        for (int i = 0; i < 4; i++) {
            int l = (int)tl0[i];
            lab[i] = l < 0 ? 0 : (l > 17 ? 17 : l);
        }
        float ss[4]  = {0.f, 0.f, 0.f, 0.f};
        float sel[4] = {0.f, 0.f, 0.f, 0.f};
#pragma unroll
        for (int c = 0; c < 18; c++) {
            float x[4]; ld4(O + (100 + c) * PS4, x);
#pragma unroll
            for (int i = 0; i < 4; i++) {
                ss[i] += __expf(x[i]);
                sel[i] = (c == lab[i]) ? x[i] : sel[i];
            }
        }
        float sk = 0.0f;
#pragma unroll
        for (int i = 0; i < 4; i++) sk += __logf(ss[i]) - sel[i];
        redAdd(s, 1, sk);
    }

    __syncthreads();
    for (int i = threadIdx.x; i < NACC; i += 256) {
        float v = s[i];
        if (v != 0.0f) atomicAdd(&g_acc[i], (double)v);
    }
}

__global__ void fin_kernel(const float* __restrict__ tar_pose, float* __restrict__ out) {
    __shared__ double sl[64], sr[64];
    const int t = threadIdx.x;  // t = b*16 + j, 64 threads

    double den = g_acc[38 + t * 7] + 1e-5;
    double ln = 0.0, rn = 0.0;
#pragma unroll
    for (int c = 0; c < 3; c++) {
        double tv  = 1.0 / (1.0 + exp(-(double)tar_pose[t * 6 + c]));
        double d   = g_acc[38 + t * 7 + 1 + c] / den - tv;
        ln += d * d;
        double tvr = 1.0 / (1.0 + exp(-(double)tar_pose[t * 6 + 3 + c]));
        double dr  = g_acc[38 + t * 7 + 4 + c] / den - tvr;
        rn += dr * dr;
    }
    sl[t] = sqrt(ln);
    sr[t] = sqrt(rn);
    __syncthreads();

    if (t == 0) {
        double L = 0.0, R = 0.0;
        for (int i = 0; i < 64; i++) { L += sl[i]; R += sr[i]; }
        double loc_loss = L / 64.0;
        double rot_loss = R / 64.0;

        const double NP = (double)BATCH * (double)HW;
        double mask_loss = -g_acc[0] / NP;
        double skin_loss =  g_acc[1] / NP;

        double nocs = 0.0, locm = 0.0, rotm = 0.0;
        for (int b = 0; b < BATCH; b++) {
            int nb = 2 + b * 9;
            for (int k = 0; k < 3; k++) {
                double ms  = g_acc[nb + k * 3 + 0];
                double cnt = g_acc[nb + k * 3 + 1];
                double ts  = g_acc[nb + k * 3 + 2];
                double per = (cnt > 0.0) ? (ms / cnt) : (ts / (double)HW);
                if (k == 0) nocs += per;
                else if (k == 1) locm += per;
                else rotm += per;
            }
        }
        nocs /= (double)BATCH; locm /= (double)BATCH; rotm /= (double)BATCH;

        out[0] = (float)nocs;
        out[1] = (float)mask_loss;
        out[2] = (float)loc_loss;
        out[3] = (float)locm;
        out[4] = (float)rot_loss;
        out[5] = (float)rotm;
        out[6] = (float)skin_loss;
    }
}

extern "C" void kernel_launch(void* const* d_in, const int* in_sizes, int n_in,
                              void* d_out, int out_size) {
    const float* outp = (const float*)d_in[0];   // output    (4,134,256,256)
    const float* tarp = (const float*)d_in[1];   // tar_maps  (4,101,256,256)
    const float* pose = (const float*)d_in[2];   // tar_pose  (4,16,6)

    zero_acc_kernel<<<2, 256>>>();
    main_kernel<<<BATCH * 64, 256>>>(outp, tarp);
    fin_kernel<<<1, 64>>>(pose, (float*)d_out);
}

// round 3
// speedup vs baseline: 1.1927x; 1.1927x over previous
#include <cuda_runtime.h>

#define BN      16
#define BATCH   4
#define HW      65536            // 256*256
#define PS4     (HW / 4)         // plane stride in float4
#define CO      134
#define CT      101
#define THRESH  0.7f

// Accumulator layout (doubles):
//  [0] mask-loss sum   [1] skin-loss sum
//  [2 + b*9 + 0..2] nocs: masked-sum, count, total-sum
//  [2 + b*9 + 3..5] loc_map: masked-sum, count, total-sum
//  [2 + b*9 + 6..8] rot_map: masked-sum, count, total-sum
//  [38 + (b*16+j)*7] pose: denom, loc_num[3], rot_num[3]
#define NACC 486

__device__ double g_acc[NACC];

__global__ void zero_acc_kernel() {
    int i = blockIdx.x * blockDim.x + threadIdx.x;
    if (i < NACC) g_acc[i] = 0.0;
}

__device__ __forceinline__ float sigm(float x) {
    return __fdividef(1.0f, 1.0f + __expf(-x));
}

__device__ __forceinline__ void ld4(const float4* __restrict__ p, float* r) {
    float4 t = *p;
    r[0] = t.x; r[1] = t.y; r[2] = t.z; r[3] = t.w;
}

// 3-level butterfly (groups of lanes ≡ mod 4), then 4-lane shared atomic
__device__ __forceinline__ void redAdd(float* s, int idx, float v) {
    v += __shfl_xor_sync(0xffffffffu, v, 16);
    v += __shfl_xor_sync(0xffffffffu, v, 8);
    v += __shfl_xor_sync(0xffffffffu, v, 4);
    if ((threadIdx.x & 31) < 4) atomicAdd(&s[idx], v);
}

__global__ __launch_bounds__(256)
void main_kernel(const float* __restrict__ outp, const float* __restrict__ tarp) {
    __shared__ float s[NACC];
    for (int i = threadIdx.x; i < NACC; i += 256) s[i] = 0.0f;
    __syncthreads();

    const int b    = blockIdx.z;
    const int role = blockIdx.y;                         // 0=misc, 1=loc, 2=rot
    const int q4   = (blockIdx.x << 8) + threadIdx.x;    // float4 index in plane

    const float4* O = (const float4*)outp + (size_t)b * CO * PS4 + q4;
    const float4* T = (const float4*)tarp + (size_t)b * CT * PS4 + q4;

    const int NB = 2 + b * 9;
    const int PB = 38 + b * 112;

    float tm[4]; ld4(T + 3 * PS4, tm);

    if (role == 0) {
        // ---- mask BCE: sum of log_sigmoid(x) - (1-tm)*x (negated in finalize) ----
        float ml[4]; ld4(O + 3 * PS4, ml);
        {
            float msum = 0.0f;
#pragma unroll
            for (int i = 0; i < 4; i++) {
                float x  = ml[i];
                float ls = fminf(x, 0.0f) - __logf(1.0f + __expf(-fabsf(x)));
                msum += ls - (1.0f - tm[i]) * x;
            }
            redAdd(s, 0, msum);
        }
        // ---- nocs masked L2 ----
        {
            float acc[4] = {0.f, 0.f, 0.f, 0.f};
#pragma unroll
            for (int c = 0; c < 3; c++) {
                float a[4], t[4];
                ld4(O + c * PS4, a);
                ld4(T + c * PS4, t);
#pragma unroll
                for (int i = 0; i < 4; i++) { float d = a[i] - t[i]; acc[i] += d * d; }
            }
            float ms = 0.f, cnt = 0.f, ts = 0.f;
#pragma unroll
            for (int i = 0; i < 4; i++) {
                float dn = sqrtf(acc[i]);
                ts += dn;
                if (tm[i] > THRESH && dn != 0.0f) { ms += dn; cnt += 1.0f; }
            }
            redAdd(s, NB + 0, ms);
            redAdd(s, NB + 1, cnt);
            redAdd(s, NB + 2, ts);
        }
        // ---- skin cross-entropy over 18 classes ----
        {
            float tl0[4]; ld4(T + 100 * PS4, tl0);
            int lab[4];
#pragma unroll
            for (int i = 0; i < 4; i++) {
                int l = (int)tl0[i];
                lab[i] = l < 0 ? 0 : (l > 17 ? 17 : l);
            }
            float ss[4]  = {0.f, 0.f, 0.f, 0.f};
            float sel[4] = {0.f, 0.f, 0.f, 0.f};
#pragma unroll
            for (int c = 0; c < 18; c++) {
                float x[4]; ld4(O + (100 + c) * PS4, x);
#pragma unroll
                for (int i = 0; i < 4; i++) {
                    ss[i] += __expf(x[i]);
                    sel[i] = (c == lab[i]) ? x[i] : sel[i];
                }
            }
            float sk = 0.0f;
#pragma unroll
            for (int i = 0; i < 4; i++) sk += __logf(ss[i]) - sel[i];
            redAdd(s, 1, sk);
        }
    } else if (role == 1) {
        // ---- loc maps: 48-dim norm + pose denominators & loc numerators ----
        float locn[4] = {0.f, 0.f, 0.f, 0.f};
#pragma unroll 1
        for (int j = 0; j < BN; j++) {
            float jsr[4]; ld4(O + (118 + j) * PS4, jsr);
            float sjm[4];
            float dsum = 0.0f;
#pragma unroll
            for (int i = 0; i < 4; i++) {
                float sj = sigm(jsr[i]) * tm[i];
                sjm[i] = sj * tm[i];
                dsum  += sj;
            }
            redAdd(s, PB + j * 7, dsum);
#pragma unroll
            for (int c = 0; c < 3; c++) {
                float pl[4], tl[4];
                ld4(O + (4 + j * 3 + c) * PS4, pl);
                ld4(T + (4 + j * 3 + c) * PS4, tl);
                float num = 0.0f;
#pragma unroll
                for (int i = 0; i < 4; i++) {
                    float p_ = sigm(pl[i]);
                    float d  = p_ - sigm(tl[i]);
                    locn[i] += d * d;
                    num += p_ * sjm[i];
                }
                redAdd(s, PB + j * 7 + 1 + c, num);
            }
        }
        float ms = 0.f, cnt = 0.f, ts = 0.f;
#pragma unroll
        for (int i = 0; i < 4; i++) {
            float dn = sqrtf(locn[i]);
            ts += dn;
            if (tm[i] > THRESH && dn != 0.0f) { ms += dn; cnt += 1.0f; }
        }
        redAdd(s, NB + 3, ms);
        redAdd(s, NB + 4, cnt);
        redAdd(s, NB + 5, ts);
    } else {
        // ---- rot maps: 48-dim norm + rot numerators (denom owned by role 1) ----
        float rotn[4] = {0.f, 0.f, 0.f, 0.f};
#pragma unroll 1
        for (int j = 0; j < BN; j++) {
            float jsr[4]; ld4(O + (118 + j) * PS4, jsr);
            float sjm[4];
#pragma unroll
            for (int i = 0; i < 4; i++) {
                float sj = sigm(jsr[i]) * tm[i];
                sjm[i] = sj * tm[i];
            }
#pragma unroll
            for (int c = 0; c < 3; c++) {
                float pr[4], tr[4];
                ld4(O + (52 + j * 3 + c) * PS4, pr);
                ld4(T + (52 + j * 3 + c) * PS4, tr);
                float num = 0.0f;
#pragma unroll
                for (int i = 0; i < 4; i++) {
                    float p_ = sigm(pr[i]);
                    float d  = p_ - sigm(tr[i]);
                    rotn[i] += d * d;
                    num += p_ * sjm[i];
                }
                redAdd(s, PB + j * 7 + 4 + c, num);
            }
        }
        float ms = 0.f, cnt = 0.f, ts = 0.f;
#pragma unroll
        for (int i = 0; i < 4; i++) {
            float dn = sqrtf(rotn[i]);
            ts += dn;
            if (tm[i] > THRESH && dn != 0.0f) { ms += dn; cnt += 1.0f; }
        }
        redAdd(s, NB + 6, ms);
        redAdd(s, NB + 7, cnt);
        redAdd(s, NB + 8, ts);
    }

    __syncthreads();
    for (int i = threadIdx.x; i < NACC; i += 256) {
        float v = s[i];
        if (v != 0.0f) atomicAdd(&g_acc[i], (double)v);
    }
}

__global__ void fin_kernel(const float* __restrict__ tar_pose, float* __restrict__ out) {
    __shared__ double sl[64], sr[64];
    const int t = threadIdx.x;  // t = b*16 + j, 64 threads

    double den = g_acc[38 + t * 7] + 1e-5;
    double ln = 0.0, rn = 0.0;
#pragma unroll
    for (int c = 0; c < 3; c++) {
        double tv  = 1.0 / (1.0 + exp(-(double)tar_pose[t * 6 + c]));
        double d   = g_acc[38 + t * 7 + 1 + c] / den - tv;
        ln += d * d;
        double tvr = 1.0 / (1.0 + exp(-(double)tar_pose[t * 6 + 3 + c]));
        double dr  = g_acc[38 + t * 7 + 4 + c] / den - tvr;
        rn += dr * dr;
    }
    sl[t] = sqrt(ln);
    sr[t] = sqrt(rn);
    __syncthreads();

    if (t == 0) {
        double L = 0.0, R = 0.0;
        for (int i = 0; i < 64; i++) { L += sl[i]; R += sr[i]; }
        double loc_loss = L / 64.0;
        double rot_loss = R / 64.0;

        const double NP = (double)BATCH * (double)HW;
        double mask_loss = -g_acc[0] / NP;
        double skin_loss =  g_acc[1] / NP;

        double nocs = 0.0, locm = 0.0, rotm = 0.0;
        for (int b = 0; b < BATCH; b++) {
            int nb = 2 + b * 9;
            for (int k = 0; k < 3; k++) {
                double ms  = g_acc[nb + k * 3 + 0];
                double cnt = g_acc[nb + k * 3 + 1];
                double ts  = g_acc[nb + k * 3 + 2];
                double per = (cnt > 0.0) ? (ms / cnt) : (ts / (double)HW);
                if (k == 0) nocs += per;
                else if (k == 1) locm += per;
                else rotm += per;
            }
        }
        nocs /= (double)BATCH; locm /= (double)BATCH; rotm /= (double)BATCH;

        out[0] = (float)nocs;
        out[1] = (float)mask_loss;
        out[2] = (float)loc_loss;
        out[3] = (float)locm;
        out[4] = (float)rot_loss;
        out[5] = (float)rotm;
        out[6] = (float)skin_loss;
    }
}

extern "C" void kernel_launch(void* const* d_in, const int* in_sizes, int n_in,
                              void* d_out, int out_size) {
    const float* outp = (const float*)d_in[0];   // output    (4,134,256,256)
    const float* tarp = (const float*)d_in[1];   // tar_maps  (4,101,256,256)
    const float* pose = (const float*)d_in[2];   // tar_pose  (4,16,6)

    zero_acc_kernel<<<2, 256>>>();
    dim3 grid(64, 3, BATCH);
    main_kernel<<<grid, 256>>>(outp, tarp);
    fin_kernel<<<1, 64>>>(pose, (float*)d_out);
}

// round 4
// speedup vs baseline: 1.2977x; 1.0881x over previous
#include <cuda_runtime.h>

#define BN      16
#define BATCH   4
#define HW      65536            // 256*256
#define PS4     (HW / 4)         // plane stride in float4
#define CO      134
#define CT      101
#define THRESH  0.7f

// Accumulator layout (doubles):
//  [0] mask-loss sum   [1] skin-loss sum
//  [2 + b*9 + 0..2] nocs: masked-sum, count, total-sum
//  [2 + b*9 + 3..5] loc_map: masked-sum, count, total-sum
//  [2 + b*9 + 6..8] rot_map: masked-sum, count, total-sum
//  [38 + (b*16+j)*7] pose: denom, loc_num[3], rot_num[3]
#define NACC 486

__device__ double g_acc[NACC];   // statically zero-initialized; fin_kernel re-zeros each call

// sigmoid via single-MUFU tanh:  sigma(x) = 0.5 + 0.5*tanh(x/2)
__device__ __forceinline__ float sigm(float x) {
    float t;
    asm("tanh.approx.f32 %0, %1;" : "=f"(t) : "f"(x * 0.5f));
    return fmaf(0.5f, t, 0.5f);
}

__device__ __forceinline__ void ld4(const float4* __restrict__ p, float* r) {
    float4 t = *p;
    r[0] = t.x; r[1] = t.y; r[2] = t.z; r[3] = t.w;
}

// 3-level butterfly (groups of lanes ≡ mod 4), then 4-lane shared atomic
__device__ __forceinline__ void redAdd(float* s, int idx, float v) {
    v += __shfl_xor_sync(0xffffffffu, v, 16);
    v += __shfl_xor_sync(0xffffffffu, v, 8);
    v += __shfl_xor_sync(0xffffffffu, v, 4);
    if ((threadIdx.x & 31) < 4) atomicAdd(&s[idx], v);
}

#define NT 128   // threads per CTA

__global__ __launch_bounds__(NT)
void main_kernel(const float* __restrict__ outp, const float* __restrict__ tarp) {
    __shared__ float s[NACC];
    for (int i = threadIdx.x; i < NACC; i += NT) s[i] = 0.0f;
    __syncthreads();

    const int b    = blockIdx.z;
    const int role = blockIdx.y;                          // 0=misc, 1=loc, 2=rot
    const int q4   = (blockIdx.x * NT) + threadIdx.x;     // float4 index in plane

    const float4* O = (const float4*)outp + (size_t)b * CO * PS4 + q4;
    const float4* T = (const float4*)tarp + (size_t)b * CT * PS4 + q4;

    const int NB = 2 + b * 9;
    const int PB = 38 + b * 112;

    float tm[4]; ld4(T + 3 * PS4, tm);

    if (role == 0) {
        // ---- mask BCE: sum of log_sigmoid(x) - (1-tm)*x (negated in finalize) ----
        float ml[4]; ld4(O + 3 * PS4, ml);
        {
            float msum = 0.0f;
#pragma unroll
            for (int i = 0; i < 4; i++) {
                float x  = ml[i];
                float ls = fminf(x, 0.0f) - __logf(1.0f + __expf(-fabsf(x)));
                msum += ls - (1.0f - tm[i]) * x;
            }
            redAdd(s, 0, msum);
        }
        // ---- nocs masked L2 ----
        {
            float acc[4] = {0.f, 0.f, 0.f, 0.f};
#pragma unroll
            for (int c = 0; c < 3; c++) {
                float a[4], t[4];
                ld4(O + c * PS4, a);
                ld4(T + c * PS4, t);
#pragma unroll
                for (int i = 0; i < 4; i++) { float d = a[i] - t[i]; acc[i] += d * d; }
            }
            float ms = 0.f, cnt = 0.f, ts = 0.f;
#pragma unroll
            for (int i = 0; i < 4; i++) {
                float dn = sqrtf(acc[i]);
                ts += dn;
                if (tm[i] > THRESH && dn != 0.0f) { ms += dn; cnt += 1.0f; }
            }
            redAdd(s, NB + 0, ms);
            redAdd(s, NB + 1, cnt);
            redAdd(s, NB + 2, ts);
        }
        // ---- skin cross-entropy over 18 classes ----
        {
            float tl0[4]; ld4(T + 100 * PS4, tl0);
            int lab[4];
#pragma unroll
            for (int i = 0; i < 4; i++) {
                int l = (int)tl0[i];
                lab[i] = l < 0 ? 0 : (l > 17 ? 17 : l);
            }
            float ss[4]  = {0.f, 0.f, 0.f, 0.f};
            float sel[4] = {0.f, 0.f, 0.f, 0.f};
#pragma unroll
            for (int c = 0; c < 18; c++) {
                float x[4]; ld4(O + (100 + c) * PS4, x);
#pragma unroll
                for (int i = 0; i < 4; i++) {
                    ss[i] += __expf(x[i]);
                    sel[i] = (c == lab[i]) ? x[i] : sel[i];
                }
            }
            float sk = 0.0f;
#pragma unroll
            for (int i = 0; i < 4; i++) sk += __logf(ss[i]) - sel[i];
            redAdd(s, 1, sk);
        }
    } else if (role == 1) {
        // ---- loc maps: 48-dim norm + pose denominators & loc numerators ----
        float locn[4] = {0.f, 0.f, 0.f, 0.f};
#pragma unroll 1
        for (int j = 0; j < BN; j++) {
            float jsr[4]; ld4(O + (118 + j) * PS4, jsr);
            float sjm[4];
            float dsum = 0.0f;
#pragma unroll
            for (int i = 0; i < 4; i++) {
                float sj = sigm(jsr[i]) * tm[i];
                sjm[i] = sj * tm[i];
                dsum  += sj;
            }
            redAdd(s, PB + j * 7, dsum);
#pragma unroll
            for (int c = 0; c < 3; c++) {
                float pl[4], tl[4];
                ld4(O + (4 + j * 3 + c) * PS4, pl);
                ld4(T + (4 + j * 3 + c) * PS4, tl);
                float num = 0.0f;
#pragma unroll
                for (int i = 0; i < 4; i++) {
                    float p_ = sigm(pl[i]);
                    float d  = p_ - sigm(tl[i]);
                    locn[i] += d * d;
                    num += p_ * sjm[i];
                }
                redAdd(s, PB + j * 7 + 1 + c, num);
            }
        }
        float ms = 0.f, cnt = 0.f, ts = 0.f;
#pragma unroll
        for (int i = 0; i < 4; i++) {
            float dn = sqrtf(locn[i]);
            ts += dn;
            if (tm[i] > THRESH && dn != 0.0f) { ms += dn; cnt += 1.0f; }
        }
        redAdd(s, NB + 3, ms);
        redAdd(s, NB + 4, cnt);
        redAdd(s, NB + 5, ts);
    } else {
        // ---- rot maps: 48-dim norm + rot numerators (denom owned by role 1) ----
        float rotn[4] = {0.f, 0.f, 0.f, 0.f};
#pragma unroll 1
        for (int j = 0; j < BN; j++) {
            float jsr[4]; ld4(O + (118 + j) * PS4, jsr);
            float sjm[4];
#pragma unroll
            for (int i = 0; i < 4; i++) {
                float sj = sigm(jsr[i]) * tm[i];
                sjm[i] = sj * tm[i];
            }
#pragma unroll
            for (int c = 0; c < 3; c++) {
                float pr[4], tr[4];
                ld4(O + (52 + j * 3 + c) * PS4, pr);
                ld4(T + (52 + j * 3 + c) * PS4, tr);
                float num = 0.0f;
#pragma unroll
                for (int i = 0; i < 4; i++) {
                    float p_ = sigm(pr[i]);
                    float d  = p_ - sigm(tr[i]);
                    rotn[i] += d * d;
                    num += p_ * sjm[i];
                }
                redAdd(s, PB + j * 7 + 4 + c, num);
            }
        }
        float ms = 0.f, cnt = 0.f, ts = 0.f;
#pragma unroll
        for (int i = 0; i < 4; i++) {
            float dn = sqrtf(rotn[i]);
            ts += dn;
            if (tm[i] > THRESH && dn != 0.0f) { ms += dn; cnt += 1.0f; }
        }
        redAdd(s, NB + 6, ms);
        redAdd(s, NB + 7, cnt);
        redAdd(s, NB + 8, ts);
    }

    __syncthreads();
    for (int i = threadIdx.x; i < NACC; i += NT) {
        float v = s[i];
        if (v != 0.0f) atomicAdd(&g_acc[i], (double)v);
    }
}

__global__ void fin_kernel(const float* __restrict__ tar_pose, float* __restrict__ out) {
    __shared__ double sl[64], sr[64];
    const int t = threadIdx.x;  // 256 threads; t<64: t = b*16 + j

    if (t < 64) {
        double den = g_acc[38 + t * 7] + 1e-5;
        double ln = 0.0, rn = 0.0;
#pragma unroll
        for (int c = 0; c < 3; c++) {
            double tv  = 1.0 / (1.0 + exp(-(double)tar_pose[t * 6 + c]));
            double d   = g_acc[38 + t * 7 + 1 + c] / den - tv;
            ln += d * d;
            double tvr = 1.0 / (1.0 + exp(-(double)tar_pose[t * 6 + 3 + c]));
            double dr  = g_acc[38 + t * 7 + 4 + c] / den - tvr;
            rn += dr * dr;
        }
        sl[t] = sqrt(ln);
        sr[t] = sqrt(rn);
    }
    __syncthreads();

    if (t == 0) {
        double L = 0.0, R = 0.0;
        for (int i = 0; i < 64; i++) { L += sl[i]; R += sr[i]; }
        double loc_loss = L / 64.0;
        double rot_loss = R / 64.0;

        const double NP = (double)BATCH * (double)HW;
        double mask_loss = -g_acc[0] / NP;
        double skin_loss =  g_acc[1] / NP;

        double nocs = 0.0, locm = 0.0, rotm = 0.0;
        for (int b = 0; b < BATCH; b++) {
            int nb = 2 + b * 9;
            for (int k = 0; k < 3; k++) {
                double ms  = g_acc[nb + k * 3 + 0];
                double cnt = g_acc[nb + k * 3 + 1];
                double ts  = g_acc[nb + k * 3 + 2];
                double per = (cnt > 0.0) ? (ms / cnt) : (ts / (double)HW);
                if (k == 0) nocs += per;
                else if (k == 1) locm += per;
                else rotm += per;
            }
        }
        nocs /= (double)BATCH; locm /= (double)BATCH; rotm /= (double)BATCH;

        out[0] = (float)nocs;
        out[1] = (float)mask_loss;
        out[2] = (float)loc_loss;
        out[3] = (float)locm;
        out[4] = (float)rot_loss;
        out[5] = (float)rotm;
        out[6] = (float)skin_loss;
    }
    __syncthreads();

    // reset accumulators for the next (graph-replayed) iteration
    for (int i = t; i < NACC; i += 256) g_acc[i] = 0.0;
}

extern "C" void kernel_launch(void* const* d_in, const int* in_sizes, int n_in,
                              void* d_out, int out_size) {
    const float* outp = (const float*)d_in[0];   // output    (4,134,256,256)
    const float* tarp = (const float*)d_in[1];   // tar_maps  (4,101,256,256)
    const float* pose = (const float*)d_in[2];   // tar_pose  (4,16,6)

    dim3 grid(HW / 4 / NT, 3, BATCH);            // (128, 3, 4)
    main_kernel<<<grid, NT>>>(outp, tarp);
    fin_kernel<<<1, 256>>>(pose, (float*)d_out);
}

// round 5
// speedup vs baseline: 1.5702x; 1.2100x over previous
#include <cuda_runtime.h>

#define BN      16
#define BATCH   4
#define HW      65536            // 256*256
#define PS4     (HW / 4)         // plane stride in float4
#define CO      134
#define CT      101
#define THRESH  0.7f

// Accumulator layout (doubles):
//  [0] mask-loss sum   [1] skin-loss sum
//  [2 + b*9 + 0..2] nocs: masked-sum, count, total-sum
//  [2 + b*9 + 3..5] loc_map: masked-sum, count, total-sum
//  [2 + b*9 + 6..8] rot_map: masked-sum, count, total-sum
//  [38 + (b*16+j)*7] pose: denom, loc_num[3], rot_num[3]
#define NACC 486

__device__ double g_acc[NACC];   // statically zero; fin_kernel re-zeros each call

// sigmoid via single-MUFU tanh:  sigma(x) = 0.5 + 0.5*tanh(x/2)
__device__ __forceinline__ float sigm(float x) {
    float t;
    asm("tanh.approx.f32 %0, %1;" : "=f"(t) : "f"(x * 0.5f));
    return fmaf(0.5f, t, 0.5f);
}

__device__ __forceinline__ void ld4(const float4* __restrict__ p, float* r) {
    float4 t = *p;
    r[0] = t.x; r[1] = t.y; r[2] = t.z; r[3] = t.w;
}

// 3-level butterfly (groups of lanes ≡ mod 4), then 4-lane shared atomic
__device__ __forceinline__ void redAdd(float* s, int idx, float v) {
    v += __shfl_xor_sync(0xffffffffu, v, 16);
    v += __shfl_xor_sync(0xffffffffu, v, 8);
    v += __shfl_xor_sync(0xffffffffu, v, 4);
    if ((threadIdx.x & 31) < 4) atomicAdd(&s[idx], v);
}

#define NT 128   // threads per CTA

__global__ __launch_bounds__(NT)
void main_kernel(const float* __restrict__ outp, const float* __restrict__ tarp) {
    __shared__ float s[NACC];
    for (int i = threadIdx.x; i < NACC; i += NT) s[i] = 0.0f;
    __syncthreads();

    const int b    = blockIdx.z;
    const int role = blockIdx.y;                          // 0=misc, 1=loc, 2=rot
    const int q4   = (blockIdx.x * NT) + threadIdx.x;     // float4 index in plane

    const float4* O = (const float4*)outp + (size_t)b * CO * PS4 + q4;
    const float4* T = (const float4*)tarp + (size_t)b * CT * PS4 + q4;

    const int NB = 2 + b * 9;
    const int PB = 38 + b * 112;

    float tm[4]; ld4(T + 3 * PS4, tm);

    if (role == 0) {
        // ---- mask BCE: sum of log_sigmoid(x) - (1-tm)*x (negated in finalize) ----
        float ml[4]; ld4(O + 3 * PS4, ml);
        {
            float msum = 0.0f;
#pragma unroll
            for (int i = 0; i < 4; i++) {
                float x  = ml[i];
                float ls = fminf(x, 0.0f) - __logf(1.0f + __expf(-fabsf(x)));
                msum += ls - (1.0f - tm[i]) * x;
            }
            redAdd(s, 0, msum);
        }
        // ---- nocs masked L2 ----
        {
            float acc[4] = {0.f, 0.f, 0.f, 0.f};
#pragma unroll
            for (int c = 0; c < 3; c++) {
                float a[4], t[4];
                ld4(O + c * PS4, a);
                ld4(T + c * PS4, t);
#pragma unroll
                for (int i = 0; i < 4; i++) { float d = a[i] - t[i]; acc[i] += d * d; }
            }
            float ms = 0.f, cnt = 0.f, ts = 0.f;
#pragma unroll
            for (int i = 0; i < 4; i++) {
                float dn = sqrtf(acc[i]);
                ts += dn;
                if (tm[i] > THRESH && dn != 0.0f) { ms += dn; cnt += 1.0f; }
            }
            redAdd(s, NB + 0, ms);
            redAdd(s, NB + 1, cnt);
            redAdd(s, NB + 2, ts);
        }
        // ---- skin cross-entropy over 18 classes ----
        {
            float tl0[4]; ld4(T + 100 * PS4, tl0);
            int lab[4];
#pragma unroll
            for (int i = 0; i < 4; i++) {
                int l = (int)tl0[i];
                lab[i] = l < 0 ? 0 : (l > 17 ? 17 : l);
            }
            float ss[4]  = {0.f, 0.f, 0.f, 0.f};
            float sel[4] = {0.f, 0.f, 0.f, 0.f};
#pragma unroll
            for (int c = 0; c < 18; c++) {
                float x[4]; ld4(O + (100 + c) * PS4, x);
#pragma unroll
                for (int i = 0; i < 4; i++) {
                    ss[i] += __expf(x[i]);
                    sel[i] = (c == lab[i]) ? x[i] : sel[i];
                }
            }
            float sk = 0.0f;
#pragma unroll
            for (int i = 0; i < 4; i++) sk += __logf(ss[i]) - sel[i];
            redAdd(s, 1, sk);
        }
    } else if (role == 1) {
        // ---- loc maps: 48-dim norm + pose denominators & loc numerators ----
        float locn[4] = {0.f, 0.f, 0.f, 0.f};
#pragma unroll 2
        for (int j = 0; j < BN; j++) {
            float jsr[4]; ld4(O + (118 + j) * PS4, jsr);
            float sjm[4];
            float dsum = 0.0f;
#pragma unroll
            for (int i = 0; i < 4; i++) {
                float sj = sigm(jsr[i]) * tm[i];
                sjm[i] = sj * tm[i];
                dsum  += sj;
            }
            redAdd(s, PB + j * 7, dsum);
#pragma unroll
            for (int c = 0; c < 3; c++) {
                float pl[4], tl[4];
                ld4(O + (4 + j * 3 + c) * PS4, pl);
                ld4(T + (4 + j * 3 + c) * PS4, tl);
                float num = 0.0f;
#pragma unroll
                for (int i = 0; i < 4; i++) {
                    float p_ = sigm(pl[i]);
                    float d  = p_ - sigm(tl[i]);
                    locn[i] += d * d;
                    num += p_ * sjm[i];
                }
                redAdd(s, PB + j * 7 + 1 + c, num);
            }
        }
        float ms = 0.f, cnt = 0.f, ts = 0.f;
#pragma unroll
        for (int i = 0; i < 4; i++) {
            float dn = sqrtf(locn[i]);
            ts += dn;
            if (tm[i] > THRESH && dn != 0.0f) { ms += dn; cnt += 1.0f; }
        }
        redAdd(s, NB + 3, ms);
        redAdd(s, NB + 4, cnt);
        redAdd(s, NB + 5, ts);
    } else {
        // ---- rot maps: 48-dim norm + rot numerators (denom owned by role 1) ----
        float rotn[4] = {0.f, 0.f, 0.f, 0.f};
#pragma unroll 2
        for (int j = 0; j < BN; j++) {
            float jsr[4]; ld4(O + (118 + j) * PS4, jsr);
            float sjm[4];
#pragma unroll
            for (int i = 0; i < 4; i++) {
                float sj = sigm(jsr[i]) * tm[i];
                sjm[i] = sj * tm[i];
            }
#pragma unroll
            for (int c = 0; c < 3; c++) {
                float pr[4], tr[4];
                ld4(O + (52 + j * 3 + c) * PS4, pr);
                ld4(T + (52 + j * 3 + c) * PS4, tr);
                float num = 0.0f;
#pragma unroll
                for (int i = 0; i < 4; i++) {
                    float p_ = sigm(pr[i]);
                    float d  = p_ - sigm(tr[i]);
                    rotn[i] += d * d;
                    num += p_ * sjm[i];
                }
                redAdd(s, PB + j * 7 + 4 + c, num);
            }
        }
        float ms = 0.f, cnt = 0.f, ts = 0.f;
#pragma unroll
        for (int i = 0; i < 4; i++) {
            float dn = sqrtf(rotn[i]);
            ts += dn;
            if (tm[i] > THRESH && dn != 0.0f) { ms += dn; cnt += 1.0f; }
        }
        redAdd(s, NB + 6, ms);
        redAdd(s, NB + 7, cnt);
        redAdd(s, NB + 8, ts);
    }

    __syncthreads();
    for (int i = threadIdx.x; i < NACC; i += NT) {
        float v = s[i];
        if (v != 0.0f) atomicAdd(&g_acc[i], (double)v);
    }
}

__global__ void fin_kernel(const float* __restrict__ tar_pose, float* __restrict__ out) {
    __shared__ float warp_l[2], warp_r[2];
    const int t = threadIdx.x;  // 256 threads; t<64: t = b*16 + j

    if (t < 64) {
        // per-joint pose norms in float (accumulator sums are O(1e3-1e4): fp32-safe)
        float den = (float)g_acc[38 + t * 7] + 1e-5f;
        float inv = __fdividef(1.0f, den);
        float ln = 0.0f, rn = 0.0f;
#pragma unroll
        for (int c = 0; c < 3; c++) {
            float tv  = __fdividef(1.0f, 1.0f + __expf(-tar_pose[t * 6 + c]));
            float d   = (float)g_acc[38 + t * 7 + 1 + c] * inv - tv;
            ln = fmaf(d, d, ln);
            float tvr = __fdividef(1.0f, 1.0f + __expf(-tar_pose[t * 6 + 3 + c]));
            float dr  = (float)g_acc[38 + t * 7 + 4 + c] * inv - tvr;
            rn = fmaf(dr, dr, rn);
        }
        float sl = sqrtf(ln);
        float sr = sqrtf(rn);
#pragma unroll
        for (int o = 16; o; o >>= 1) {
            sl += __shfl_xor_sync(0xffffffffu, sl, o);
            sr += __shfl_xor_sync(0xffffffffu, sr, o);
        }
        if ((t & 31) == 0) { warp_l[t >> 5] = sl; warp_r[t >> 5] = sr; }
    }
    __syncthreads();

    if (t == 0) {
        double loc_loss = (double)(warp_l[0] + warp_l[1]) / 64.0;
        double rot_loss = (double)(warp_r[0] + warp_r[1]) / 64.0;

        const double NP = (double)BATCH * (double)HW;
        double mask_loss = -g_acc[0] / NP;
        double skin_loss =  g_acc[1] / NP;

        double nocs = 0.0, locm = 0.0, rotm = 0.0;
#pragma unroll
        for (int b = 0; b < BATCH; b++) {
            int nb = 2 + b * 9;
#pragma unroll
            for (int k = 0; k < 3; k++) {
                double ms  = g_acc[nb + k * 3 + 0];
                double cnt = g_acc[nb + k * 3 + 1];
                double ts  = g_acc[nb + k * 3 + 2];
                double per = (cnt > 0.0) ? (ms / cnt) : (ts / (double)HW);
                if (k == 0) nocs += per;
                else if (k == 1) locm += per;
                else rotm += per;
            }
        }
        nocs /= (double)BATCH; locm /= (double)BATCH; rotm /= (double)BATCH;

        out[0] = (float)nocs;
        out[1] = (float)mask_loss;
        out[2] = (float)loc_loss;
        out[3] = (float)locm;
        out[4] = (float)rot_loss;
        out[5] = (float)rotm;
        out[6] = (float)skin_loss;
    }
    __syncthreads();

    // reset accumulators for the next (graph-replayed) iteration
    for (int i = t; i < NACC; i += 256) g_acc[i] = 0.0;
}

extern "C" void kernel_launch(void* const* d_in, const int* in_sizes, int n_in,
                              void* d_out, int out_size) {
    const float* outp = (const float*)d_in[0];   // output    (4,134,256,256)
    const float* tarp = (const float*)d_in[1];   // tar_maps  (4,101,256,256)
    const float* pose = (const float*)d_in[2];   // tar_pose  (4,16,6)

    dim3 grid(HW / 4 / NT, 3, BATCH);            // (128, 3, 4)
    main_kernel<<<grid, NT>>>(outp, tarp);
    fin_kernel<<<1, 256>>>(pose, (float*)d_out);
}

// round 6
// speedup vs baseline: 1.9180x; 1.2215x over previous
#include <cuda_runtime.h>

#define BN      16
#define BATCH   4
#define HW      65536            // 256*256
#define PS4     (HW / 4)         // plane stride in float4
#define CO      134
#define CT      101
#define THRESH  0.7f

// Accumulator layout (doubles):
//  [0] mask-loss sum   [1] skin-loss sum
//  [2 + b*9 + 0..2] nocs: masked-sum, count, total-sum
//  [2 + b*9 + 3..5] loc_map: masked-sum, count, total-sum
//  [2 + b*9 + 6..8] rot_map: masked-sum, count, total-sum
//  [38 + (b*16+j)*7] pose: denom, loc_num[3], rot_num[3]
#define NACC 486

__device__ double g_acc[NACC];        // statically zero; last block re-zeros each call
__device__ unsigned int g_count = 0;  // CTA completion counter; last block resets

// sigmoid via single-MUFU tanh:  sigma(x) = 0.5 + 0.5*tanh(x/2)
__device__ __forceinline__ float sigm(float x) {
    float t;
    asm("tanh.approx.f32 %0, %1;" : "=f"(t) : "f"(x * 0.5f));
    return fmaf(0.5f, t, 0.5f);
}

__device__ __forceinline__ void ld4(const float4* __restrict__ p, float* r) {
    float4 t = *p;
    r[0] = t.x; r[1] = t.y; r[2] = t.z; r[3] = t.w;
}

// full 5-level butterfly, single-lane shared atomic
__device__ __forceinline__ void redAdd(float* s, int idx, float v) {
    v += __shfl_xor_sync(0xffffffffu, v, 16);
    v += __shfl_xor_sync(0xffffffffu, v, 8);
    v += __shfl_xor_sync(0xffffffffu, v, 4);
    v += __shfl_xor_sync(0xffffffffu, v, 2);
    v += __shfl_xor_sync(0xffffffffu, v, 1);
    if ((threadIdx.x & 31) == 0) atomicAdd(&s[idx], v);
}

#define NT 128          // threads per CTA
#define NCTA (128*3*4)  // total CTAs

__global__ __launch_bounds__(NT)
void main_kernel(const float* __restrict__ outp, const float* __restrict__ tarp,
                 const float* __restrict__ tar_pose, float* __restrict__ out) {
    __shared__ float s[NACC];
    __shared__ bool  is_last;
    for (int i = threadIdx.x; i < NACC; i += NT) s[i] = 0.0f;
    __syncthreads();

    const int b    = blockIdx.z;
    const int role = blockIdx.y;                          // 0=misc, 1=loc, 2=rot
    const int q4   = (blockIdx.x * NT) + threadIdx.x;     // float4 index in plane

    const float4* O = (const float4*)outp + (size_t)b * CO * PS4 + q4;
    const float4* T = (const float4*)tarp + (size_t)b * CT * PS4 + q4;

    const int NB = 2 + b * 9;
    const int PB = 38 + b * 112;

    float tm[4]; ld4(T + 3 * PS4, tm);

    if (role == 0) {
        // ---- mask BCE: sum of log_sigmoid(x) - (1-tm)*x (negated in finalize) ----
        float ml[4]; ld4(O + 3 * PS4, ml);
        {
            float msum = 0.0f;
#pragma unroll
            for (int i = 0; i < 4; i++) {
                float x  = ml[i];
                float ls = fminf(x, 0.0f) - __logf(1.0f + __expf(-fabsf(x)));
                msum += ls - (1.0f - tm[i]) * x;
            }
            redAdd(s, 0, msum);
        }
        // ---- nocs masked L2 ----
        {
            float acc[4] = {0.f, 0.f, 0.f, 0.f};
#pragma unroll
            for (int c = 0; c < 3; c++) {
                float a[4], t[4];
                ld4(O + c * PS4, a);
                ld4(T + c * PS4, t);
#pragma unroll
                for (int i = 0; i < 4; i++) { float d = a[i] - t[i]; acc[i] += d * d; }
            }
            float ms = 0.f, cnt = 0.f, ts = 0.f;
#pragma unroll
            for (int i = 0; i < 4; i++) {
                float dn = sqrtf(acc[i]);
                ts += dn;
                if (tm[i] > THRESH && dn != 0.0f) { ms += dn; cnt += 1.0f; }
            }
            redAdd(s, NB + 0, ms);
            redAdd(s, NB + 1, cnt);
            redAdd(s, NB + 2, ts);
        }
        // ---- skin cross-entropy over 18 classes ----
        {
            float tl0[4]; ld4(T + 100 * PS4, tl0);
            int lab[4];
#pragma unroll
            for (int i = 0; i < 4; i++) {
                int l = (int)tl0[i];
                lab[i] = l < 0 ? 0 : (l > 17 ? 17 : l);
            }
            float ss[4]  = {0.f, 0.f, 0.f, 0.f};
            float sel[4] = {0.f, 0.f, 0.f, 0.f};
#pragma unroll
            for (int c = 0; c < 18; c++) {
                float x[4]; ld4(O + (100 + c) * PS4, x);
#pragma unroll
                for (int i = 0; i < 4; i++) {
                    ss[i] += __expf(x[i]);
                    sel[i] = (c == lab[i]) ? x[i] : sel[i];
                }
            }
            float sk = 0.0f;
#pragma unroll
            for (int i = 0; i < 4; i++) sk += __logf(ss[i]) - sel[i];
            redAdd(s, 1, sk);
        }
    } else if (role == 1) {
        // ---- loc maps: 48-dim norm + pose denominators & loc numerators ----
        float locn[4] = {0.f, 0.f, 0.f, 0.f};
#pragma unroll 2
        for (int j = 0; j < BN; j++) {
            float jsr[4]; ld4(O + (118 + j) * PS4, jsr);
            float sjm[4];
            float dsum = 0.0f;
#pragma unroll
            for (int i = 0; i < 4; i++) {
                float sj = sigm(jsr[i]) * tm[i];
                sjm[i] = sj * tm[i];
                dsum  += sj;
            }
            redAdd(s, PB + j * 7, dsum);
#pragma unroll
            for (int c = 0; c < 3; c++) {
                float pl[4], tl[4];
                ld4(O + (4 + j * 3 + c) * PS4, pl);
                ld4(T + (4 + j * 3 + c) * PS4, tl);
                float num = 0.0f;
#pragma unroll
                for (int i = 0; i < 4; i++) {
                    float p_ = sigm(pl[i]);
                    float d  = p_ - sigm(tl[i]);
                    locn[i] += d * d;
                    num += p_ * sjm[i];
                }
                redAdd(s, PB + j * 7 + 1 + c, num);
            }
        }
        float ms = 0.f, cnt = 0.f, ts = 0.f;
#pragma unroll
        for (int i = 0; i < 4; i++) {
            float dn = sqrtf(locn[i]);
            ts += dn;
            if (tm[i] > THRESH && dn != 0.0f) { ms += dn; cnt += 1.0f; }
        }
        redAdd(s, NB + 3, ms);
        redAdd(s, NB + 4, cnt);
        redAdd(s, NB + 5, ts);
    } else {
        // ---- rot maps: 48-dim norm + rot numerators (denom owned by role 1) ----
        float rotn[4] = {0.f, 0.f, 0.f, 0.f};
#pragma unroll 2
        for (int j = 0; j < BN; j++) {
            float jsr[4]; ld4(O + (118 + j) * PS4, jsr);
            float sjm[4];
#pragma unroll
            for (int i = 0; i < 4; i++) {
                float sj = sigm(jsr[i]) * tm[i];
                sjm[i] = sj * tm[i];
            }
#pragma unroll
            for (int c = 0; c < 3; c++) {
                float pr[4], tr[4];
                ld4(O + (52 + j * 3 + c) * PS4, pr);
                ld4(T + (52 + j * 3 + c) * PS4, tr);
                float num = 0.0f;
#pragma unroll
                for (int i = 0; i < 4; i++) {
                    float p_ = sigm(pr[i]);
                    float d  = p_ - sigm(tr[i]);
                    rotn[i] += d * d;
                    num += p_ * sjm[i];
                }
                redAdd(s, PB + j * 7 + 4 + c, num);
            }
        }
        float ms = 0.f, cnt = 0.f, ts = 0.f;
#pragma unroll
        for (int i = 0; i < 4; i++) {
            float dn = sqrtf(rotn[i]);
            ts += dn;
            if (tm[i] > THRESH && dn != 0.0f) { ms += dn; cnt += 1.0f; }
        }
        redAdd(s, NB + 6, ms);
        redAdd(s, NB + 7, cnt);
        redAdd(s, NB + 8, ts);
    }

    __syncthreads();
    for (int i = threadIdx.x; i < NACC; i += NT) {
        float v = s[i];
        if (v != 0.0f) atomicAdd(&g_acc[i], (double)v);
    }

    // ---- last-block finalize ----
    __threadfence();
    if (threadIdx.x == 0) {
        unsigned int prev = atomicAdd(&g_count, 1u);
        is_last = (prev == NCTA - 1u);
    }
    __syncthreads();
    if (!is_last) return;
    __threadfence();  // acquire: see all CTAs' g_acc writes

    const int t = threadIdx.x;  // 128 threads
    __shared__ float warp_l[2], warp_r[2];

    if (t < 64) {
        // per-joint pose norms in fp32 (accumulator sums are O(1e3-1e4): fp32-safe)
        float den = (float)g_acc[38 + t * 7] + 1e-5f;
        float inv = __fdividef(1.0f, den);
        float ln = 0.0f, rn = 0.0f;
#pragma unroll
        for (int c = 0; c < 3; c++) {
            float tv  = __fdividef(1.0f, 1.0f + __expf(-tar_pose[t * 6 + c]));
            float d   = (float)g_acc[38 + t * 7 + 1 + c] * inv - tv;
            ln = fmaf(d, d, ln);
            float tvr = __fdividef(1.0f, 1.0f + __expf(-tar_pose[t * 6 + 3 + c]));
            float dr  = (float)g_acc[38 + t * 7 + 4 + c] * inv - tvr;
            rn = fmaf(dr, dr, rn);
        }
        float sl = sqrtf(ln);
        float sr = sqrtf(rn);
#pragma unroll
        for (int o = 16; o; o >>= 1) {
            sl += __shfl_xor_sync(0xffffffffu, sl, o);
            sr += __shfl_xor_sync(0xffffffffu, sr, o);
        }
        if ((t & 31) == 0) { warp_l[t >> 5] = sl; warp_r[t >> 5] = sr; }
    }
    __syncthreads();

    if (t == 0) {
        double loc_loss = (double)(warp_l[0] + warp_l[1]) / 64.0;
        double rot_loss = (double)(warp_r[0] + warp_r[1]) / 64.0;

        const double NP = (double)BATCH * (double)HW;
        double mask_loss = -g_acc[0] / NP;
        double skin_loss =  g_acc[1] / NP;

        double nocs = 0.0, locm = 0.0, rotm = 0.0;
#pragma unroll
        for (int b2 = 0; b2 < BATCH; b2++) {
            int nb = 2 + b2 * 9;
#pragma unroll
            for (int k = 0; k < 3; k++) {
                double ms  = g_acc[nb + k * 3 + 0];
                double cnt = g_acc[nb + k * 3 + 1];
                double ts  = g_acc[nb + k * 3 + 2];
                double per = (cnt > 0.0) ? (ms / cnt) : (ts / (double)HW);
                if (k == 0) nocs += per;
                else if (k == 1) locm += per;
                else rotm += per;
            }
        }
        nocs /= (double)BATCH; locm /= (double)BATCH; rotm /= (double)BATCH;

        out[0] = (float)nocs;
        out[1] = (float)mask_loss;
        out[2] = (float)loc_loss;
        out[3] = (float)locm;
        out[4] = (float)rot_loss;
        out[5] = (float)rotm;
        out[6] = (float)skin_loss;
    }
    __syncthreads();

    // reset for next graph replay
    for (int i = t; i < NACC; i += NT) g_acc[i] = 0.0;
    if (t == 0) g_count = 0u;
}

extern "C" void kernel_launch(void* const* d_in, const int* in_sizes, int n_in,
                              void* d_out, int out_size) {
    const float* outp = (const float*)d_in[0];   // output    (4,134,256,256)
    const float* tarp = (const float*)d_in[1];   // tar_maps  (4,101,256,256)
    const float* pose = (const float*)d_in[2];   // tar_pose  (4,16,6)

    dim3 grid(HW / 4 / NT, 3, BATCH);            // (128, 3, 4) = 1536 CTAs
    main_kernel<<<grid, NT>>>(outp, tarp, pose, (float*)d_out);
}